// round 17
// baseline (speedup 1.0000x reference)
#include <cuda_runtime.h>
#include <cuda_bf16.h>
#include <math.h>
#include <cstdint>

// ---------------- problem constants ----------------
#define Hh    128
#define Ww    256
#define Bn    2
#define COUT  144
#define CIN_1 513
#define CINP1 576     // 513 padded (rows are 16-multiples for k16 steps)
#define CINP2 192     // 144 padded
#define DSf   4
#define HWsz  (Hh*Ww)
#define NPIX  (Bn*HWsz)

typedef unsigned long long ull;

// ---------------- persistent scratch (zero-initialized device globals) ------
__device__ __nv_bfloat16 g_x0h[(size_t)NPIX*CINP1];
__device__ __nv_bfloat16 g_x0l[(size_t)NPIX*CINP1];
__device__ __nv_bfloat16 g_y1h[(size_t)NPIX*CINP2];
__device__ __nv_bfloat16 g_y1l[(size_t)NPIX*CINP2];
__device__ __nv_bfloat16 g_y2h[(size_t)NPIX*CINP2];
__device__ __nv_bfloat16 g_y2l[(size_t)NPIX*CINP2];
__device__ float         g_x3 [(size_t)NPIX*COUT];
__device__ __nv_bfloat16 g_w1h[(size_t)9*COUT*CINP1];
__device__ __nv_bfloat16 g_w1l[(size_t)9*COUT*CINP1];
__device__ __nv_bfloat16 g_w2h[(size_t)9*COUT*CINP2];
__device__ __nv_bfloat16 g_w2l[(size_t)9*COUT*CINP2];
__device__ __nv_bfloat16 g_w3h[(size_t)9*COUT*CINP2];
__device__ __nv_bfloat16 g_w3l[(size_t)9*COUT*CINP2];

// ---------------- helpers ----------------------------------------------------
__device__ __forceinline__ void bf_split(float v, __nv_bfloat16& h, __nv_bfloat16& l) {
    h = __float2bfloat16(v);
    l = __float2bfloat16(v - __bfloat162float(h));
}
__device__ __forceinline__ uint32_t ld_u32(const __nv_bfloat16* p) {
    return *(const uint32_t*)p;   // 2 bf16, 4B-aligned by construction
}
// m16n8k16 row.col bf16 -> f32 accumulate (sm_80 baseline PTX, no 'a' features)
__device__ __forceinline__ void mma16816(float* c,
                                         uint32_t a0, uint32_t a1, uint32_t a2, uint32_t a3,
                                         uint32_t b0, uint32_t b1) {
    asm volatile(
        "mma.sync.aligned.m16n8k16.row.col.f32.bf16.bf16.f32 "
        "{%0,%1,%2,%3}, {%4,%5,%6,%7}, {%8,%9}, {%0,%1,%2,%3};"
        : "+f"(c[0]), "+f"(c[1]), "+f"(c[2]), "+f"(c[3])
        : "r"(a0), "r"(a1), "r"(a2), "r"(a3), "r"(b0), "r"(b1));
}

// ---------------------------------------------------------------------------
// prep_in: concat(disp, space_to_depth(fea)) -> HWC-padded bf16 hi/lo.
// Pad channels [513..575] stay zero (zero-initialized globals, never written).
// ---------------------------------------------------------------------------
__global__ void prep_in(const float* __restrict__ disp,
                        const float* __restrict__ fea) {
    size_t idx = (size_t)blockIdx.x * blockDim.x + threadIdx.x;
    size_t total = (size_t)NPIX * 129;
    if (idx >= total) return;
    int task = (int)(idx % 129);
    size_t pix = idx / 129;
    int w = (int)(pix % Ww);
    int h = (int)((pix / Ww) % Hh);
    int b = (int)(pix / HWsz);
    __nv_bfloat16 hb, lb;
    if (task == 0) {
        bf_split(disp[pix], hb, lb);
        g_x0h[pix*CINP1] = hb; g_x0l[pix*CINP1] = lb;
    } else {
        int ti = task - 1;
        int c = ti >> 2, i = ti & 3;
        const float* fp = fea + (((size_t)(b*32 + c))*(Hh*DSf) + h*DSf + i)*(Ww*DSf) + (size_t)w*DSf;
        int cip = 1 + ti*4;
        float4 v = *(const float4*)fp;
        bf_split(v.x, hb, lb); g_x0h[pix*CINP1+cip+0]=hb; g_x0l[pix*CINP1+cip+0]=lb;
        bf_split(v.y, hb, lb); g_x0h[pix*CINP1+cip+1]=hb; g_x0l[pix*CINP1+cip+1]=lb;
        bf_split(v.z, hb, lb); g_x0h[pix*CINP1+cip+2]=hb; g_x0l[pix*CINP1+cip+2]=lb;
        bf_split(v.w, hb, lb); g_x0h[pix*CINP1+cip+3]=hb; g_x0l[pix*CINP1+cip+3]=lb;
    }
}

// ---------------------------------------------------------------------------
// prep_w: wt[oc][ci][3][3] -> tap-major bf16 hi/lo [tap][oc][CINP]
// ---------------------------------------------------------------------------
template<int CIN, int CINP>
__global__ void prep_w(const float* __restrict__ w,
                       __nv_bfloat16* __restrict__ th,
                       __nv_bfloat16* __restrict__ tl) {
    size_t idx = (size_t)blockIdx.x * blockDim.x + threadIdx.x;
    size_t total = (size_t)9 * COUT * CIN;
    if (idx >= total) return;
    int cip = (int)(idx % CIN);
    int oc  = (int)((idx / CIN) % COUT);
    int tap = (int)(idx / ((size_t)CIN * COUT));
    float v = w[((size_t)oc*CIN + cip)*9 + tap];
    __nv_bfloat16 hb, lb; bf_split(v, hb, lb);
    size_t o = ((size_t)tap*COUT + oc)*CINP + cip;
    th[o] = hb; tl[o] = lb;
}

// ---------------------------------------------------------------------------
// conv_hmma: implicit-GEMM 3x3 conv via mma.sync bf16 hi/lo (3 terms) + BN.
// Block = 64 consecutive pixels (same image row) x 144 oc; 8 warps (4M x 2N).
// Warp tile m16 x n72 (9 n8 frags). Fragments loaded directly from gmem
// (per-(tap,k16) working sets are L1-resident). grid = NPIX/64 = 1024.
// ---------------------------------------------------------------------------
template<int CINP, bool RELU, bool FP32OUT>
__global__ void __launch_bounds__(256)
conv_hmma(const __nv_bfloat16* __restrict__ xh,
          const __nv_bfloat16* __restrict__ xl,
          const __nv_bfloat16* __restrict__ wh,
          const __nv_bfloat16* __restrict__ wl,
          const float* __restrict__ gam,
          const float* __restrict__ bet,
          __nv_bfloat16* __restrict__ oh,
          __nv_bfloat16* __restrict__ ol,
          float* __restrict__ of)
{
    const int t    = threadIdx.x;
    const int lane = t & 31;
    const int wid  = t >> 5;
    const int wm   = wid & 3;          // M quarter: rows [wm*16, wm*16+15]
    const int wn   = wid >> 2;         // N half:    ocs  [wn*72, wn*72+71]
    const int g    = lane >> 2;        // 0..7
    const int tg   = lane & 3;         // 0..3

    const int p0 = blockIdx.x * 64;    // 64 consecutive pixels, same h (64 | 256)
    const int b  = p0 / HWsz;
    const int rm = p0 % HWsz;
    const int h  = rm / Ww;
    const int w0 = rm % Ww;

    const int r0 = wm*16 + g;          // block-row of A frag rows
    const int r1 = r0 + 8;

    float acc[9][4];
#pragma unroll
    for (int f = 0; f < 9; f++) {
        acc[f][0] = 0.f; acc[f][1] = 0.f; acc[f][2] = 0.f; acc[f][3] = 0.f;
    }

#pragma unroll 1
    for (int tap = 0; tap < 9; tap++) {
        const int ky = tap/3 - 1, kx = tap%3 - 1;
        const int hp = h + ky;
        const bool vh = ((unsigned)hp < (unsigned)Hh);
        const int wA0 = w0 + r0 + kx;
        const int wA1 = w0 + r1 + kx;
        const bool v0 = vh && ((unsigned)wA0 < (unsigned)Ww);
        const bool v1 = vh && ((unsigned)wA1 < (unsigned)Ww);
        const size_t a0b = v0 ? ((size_t)b*HWsz + (size_t)hp*Ww + wA0)*(size_t)CINP : 0;
        const size_t a1b = v1 ? ((size_t)b*HWsz + (size_t)hp*Ww + wA1)*(size_t)CINP : 0;
        const __nv_bfloat16* wth = wh + (size_t)tap*COUT*CINP;
        const __nv_bfloat16* wtl = wl + (size_t)tap*COUT*CINP;

#pragma unroll 1
        for (int k0 = 0; k0 < CINP; k0 += 16) {
            const int ka = k0 + 2*tg;
            // A fragments (hi and lo): rows (r0, r1) x k-halves (ka, ka+8)
            uint32_t ah0 = v0 ? ld_u32(xh + a0b + ka)     : 0u;
            uint32_t ah1 = v1 ? ld_u32(xh + a1b + ka)     : 0u;
            uint32_t ah2 = v0 ? ld_u32(xh + a0b + ka + 8) : 0u;
            uint32_t ah3 = v1 ? ld_u32(xh + a1b + ka + 8) : 0u;
            uint32_t al0 = v0 ? ld_u32(xl + a0b + ka)     : 0u;
            uint32_t al1 = v1 ? ld_u32(xl + a1b + ka)     : 0u;
            uint32_t al2 = v0 ? ld_u32(xl + a0b + ka + 8) : 0u;
            uint32_t al3 = v1 ? ld_u32(xl + a1b + ka + 8) : 0u;
#pragma unroll
            for (int f = 0; f < 9; f++) {
                const int oc = wn*72 + f*8 + g;
                const size_t wb = (size_t)oc*CINP + ka;
                uint32_t bh0 = ld_u32(wth + wb);
                uint32_t bh1 = ld_u32(wth + wb + 8);
                uint32_t bl0 = ld_u32(wtl + wb);
                uint32_t bl1 = ld_u32(wtl + wb + 8);
                mma16816(acc[f], ah0, ah1, ah2, ah3, bh0, bh1);   // hi*hi
                mma16816(acc[f], ah0, ah1, ah2, ah3, bl0, bl1);   // hi*lo
                mma16816(acc[f], al0, al1, al2, al3, bh0, bh1);   // lo*hi
            }
        }
    }

    // ---- epilogue: BN (+ReLU), write HWC outputs
    // acc[f]: c0=(r0, oc0) c1=(r0, oc0+1) c2=(r1, oc0) c3=(r1, oc0+1)
    const float inv = rsqrtf(1.0f + 1e-5f);
    const size_t pix0 = (size_t)p0 + r0;   // pixels are consecutive: p0 + row
    const size_t pix1 = (size_t)p0 + r1;
#pragma unroll
    for (int f = 0; f < 9; f++) {
        const int oc0 = wn*72 + f*8 + 2*tg;
        const float s0 = __ldg(gam + oc0)     * inv, z0 = __ldg(bet + oc0);
        const float s1 = __ldg(gam + oc0 + 1) * inv, z1 = __ldg(bet + oc0 + 1);
        float v00 = acc[f][0]*s0 + z0, v01 = acc[f][1]*s1 + z1;
        float v10 = acc[f][2]*s0 + z0, v11 = acc[f][3]*s1 + z1;
        if (RELU) {
            v00 = fmaxf(v00, 0.f); v01 = fmaxf(v01, 0.f);
            v10 = fmaxf(v10, 0.f); v11 = fmaxf(v11, 0.f);
        }
        if (FP32OUT) {
            *(float2*)(of + pix0*COUT + oc0) = make_float2(v00, v01);
            *(float2*)(of + pix1*COUT + oc0) = make_float2(v10, v11);
        } else {
            __nv_bfloat16 h0, l0, h1, l1;
            bf_split(v00, h0, l0); bf_split(v01, h1, l1);
            *(__nv_bfloat162*)(oh + pix0*CINP2 + oc0) = __nv_bfloat162(h0, h1);
            *(__nv_bfloat162*)(ol + pix0*CINP2 + oc0) = __nv_bfloat162(l0, l1);
            bf_split(v10, h0, l0); bf_split(v11, h1, l1);
            *(__nv_bfloat162*)(oh + pix1*CINP2 + oc0) = __nv_bfloat162(h0, h1);
            *(__nv_bfloat162*)(ol + pix1*CINP2 + oc0) = __nv_bfloat162(l0, l1);
        }
    }
}

// ---------------------------------------------------------------------------
// finalize: softmax over 9 logits x16, disparity blend, pixel-shuffle. x3 HWC.
// ---------------------------------------------------------------------------
__global__ void finalize_kernel(const float* __restrict__ x3,
                                const float* __restrict__ disp,
                                float* __restrict__ out) {
    int idx = blockIdx.x * blockDim.x + threadIdx.x;
    if (idx >= Bn*HWsz) return;
    int w = idx % Ww;
    int h = (idx / Ww) % Hh;
    int b = idx / HWsz;

    float nb[9];
#pragma unroll
    for (int dy = 0; dy < 3; dy++) {
        int hh = min(max(h + dy - 1, 0), Hh-1);
#pragma unroll
        for (int dx = 0; dx < 3; dx++) {
            int ww = min(max(w + dx - 1, 0), Ww-1);
            nb[dy*3+dx] = __ldg(disp + ((size_t)b*Hh + hh)*Ww + ww);
        }
    }
    const float* xp = x3 + (size_t)idx * COUT;
    float* ob = out + (size_t)b*(Hh*DSf)*(Ww*DSf);

#pragma unroll
    for (int ds = 0; ds < 16; ds++) {
        float v[9];
        float mx = -3.4e38f;
#pragma unroll
        for (int k = 0; k < 9; k++) {
            v[k] = __ldg(xp + ds*9 + k);
            mx = fmaxf(mx, v[k]);
        }
        float se = 0.0f, r = 0.0f;
#pragma unroll
        for (int k = 0; k < 9; k++) {
            float e = expf(v[k] - mx);
            se += e;
            r = fmaf(e, nb[k], r);
        }
        r = r / se * (float)DSf;
        int i = ds >> 2, j = ds & 3;
        ob[(size_t)(h*DSf + i)*(Ww*DSf) + (size_t)w*DSf + j] = r;
    }
}

// ---------------------------------------------------------------------------
extern "C" void kernel_launch(void* const* d_in, const int* in_sizes, int n_in,
                              void* d_out, int out_size) {
    (void)in_sizes; (void)n_in; (void)out_size;
    const float* disp = (const float*)d_in[0];
    const float* fea  = (const float*)d_in[1];
    const float* w1 = (const float*)d_in[2];
    const float* g1 = (const float*)d_in[3];
    const float* b1 = (const float*)d_in[4];
    const float* w2 = (const float*)d_in[5];
    const float* g2 = (const float*)d_in[6];
    const float* b2 = (const float*)d_in[7];
    const float* w3 = (const float*)d_in[8];
    const float* g3 = (const float*)d_in[9];
    const float* b3 = (const float*)d_in[10];
    float* out = (float*)d_out;

    __nv_bfloat16 *x0h, *x0l, *y1h, *y1l, *y2h, *y2l;
    __nv_bfloat16 *w1h, *w1l, *w2h, *w2l, *w3h, *w3l;
    float* x3;
    cudaGetSymbolAddress((void**)&x0h, g_x0h); cudaGetSymbolAddress((void**)&x0l, g_x0l);
    cudaGetSymbolAddress((void**)&y1h, g_y1h); cudaGetSymbolAddress((void**)&y1l, g_y1l);
    cudaGetSymbolAddress((void**)&y2h, g_y2h); cudaGetSymbolAddress((void**)&y2l, g_y2l);
    cudaGetSymbolAddress((void**)&w1h, g_w1h); cudaGetSymbolAddress((void**)&w1l, g_w1l);
    cudaGetSymbolAddress((void**)&w2h, g_w2h); cudaGetSymbolAddress((void**)&w2l, g_w2l);
    cudaGetSymbolAddress((void**)&w3h, g_w3h); cudaGetSymbolAddress((void**)&w3l, g_w3l);
    cudaGetSymbolAddress((void**)&x3,  g_x3);

    // 1) input -> HWC bf16 hi/lo
    {
        size_t n = (size_t)NPIX * 129;
        prep_in<<<(unsigned)((n + 255)/256), 256>>>(disp, fea);
    }
    // 2) weights -> tap-major bf16 hi/lo
    {
        size_t n1 = (size_t)9*COUT*CIN_1;
        prep_w<CIN_1, CINP1><<<(unsigned)((n1 + 255)/256), 256>>>(w1, w1h, w1l);
        size_t n2 = (size_t)9*COUT*COUT;
        prep_w<COUT, CINP2><<<(unsigned)((n2 + 255)/256), 256>>>(w2, w2h, w2l);
        prep_w<COUT, CINP2><<<(unsigned)((n2 + 255)/256), 256>>>(w3, w3h, w3l);
    }
    // 3) three HMMA convs (1024 pixel-tiles each)
    conv_hmma<CINP1, true,  false><<<NPIX/64, 256>>>(x0h, x0l, w1h, w1l, g1, b1, y1h, y1l, nullptr);
    conv_hmma<CINP2, true,  false><<<NPIX/64, 256>>>(y1h, y1l, w2h, w2l, g2, b2, y2h, y2l, nullptr);
    conv_hmma<CINP2, false, true ><<<NPIX/64, 256>>>(y2h, y2l, w3h, w3l, g3, b3, nullptr, nullptr, x3);
    // 4) softmax + blend + pixel shuffle
    finalize_kernel<<<(Bn*HWsz + 127)/128, 128>>>(x3, disp, out);
}